// round 1
// baseline (speedup 1.0000x reference)
#include <cuda_runtime.h>
#include <math.h>

#define NB 8   // batch

// ---------------- scratch (device globals; no allocation allowed) ----------------
// pyramid: sum over levels of 8*3*(8<<l)*(14<<l), l=0..5  = 3,669,120 floats
__device__ float g_pyr_ref[3669120];
__device__ float g_pyr_supp[3669120];
// ping-pong activation buffers: max 8*64*256*448 = 58,720,256 floats (~235 MB each)
__device__ float g_bufA[58720256];
__device__ float g_bufB[58720256];
// flow buffers at finest resolution: 8*2*256*448
__device__ float g_flow[1835008];
__device__ float g_flowup[1835008];

// ---------------- small elementwise kernels ----------------
__global__ void k_normalize(const float* __restrict__ ref, const float* __restrict__ supp,
                            float* __restrict__ oref, float* __restrict__ osupp,
                            int total, int HW) {
    int i = blockIdx.x * blockDim.x + threadIdx.x;
    if (i >= total) return;
    int c = (i / HW) % 3;
    const float mean[3] = {0.485f, 0.456f, 0.406f};
    const float stdv[3] = {0.229f, 0.224f, 0.225f};
    oref[i]  = (ref[i]  - mean[c]) / stdv[c];
    osupp[i] = (supp[i] - mean[c]) / stdv[c];
}

// out dims H,W ; in dims 2H,2W
__global__ void k_avgpool(const float* __restrict__ in, float* __restrict__ out,
                          int total, int H, int W) {
    int i = blockIdx.x * blockDim.x + threadIdx.x;
    if (i >= total) return;
    int x = i % W;
    int y = (i / W) % H;
    int nc = i / (W * H);
    const float* p = in + (size_t)nc * (4 * H * W) + (size_t)(2 * y) * (2 * W) + 2 * x;
    out[i] = 0.25f * (p[0] + p[1] + p[2 * W] + p[2 * W + 1]);
}

__global__ void k_zero(float* p, int total) {
    int i = blockIdx.x * blockDim.x + threadIdx.x;
    if (i < total) p[i] = 0.f;
}

// bilinear x2 upsample (align-corners linspace), then scale by 2.0
// in: (NB,2,h,w) -> out: (NB,2,2h,2w)
__global__ void k_upflow(const float* __restrict__ in, float* __restrict__ out,
                         int h, int w) {
    int H = 2 * h, W = 2 * w;
    int total = NB * 2 * H * W;
    int i = blockIdx.x * blockDim.x + threadIdx.x;
    if (i >= total) return;
    int x = i % W;
    int y = (i / W) % H;
    int nc = i / (W * H);
    float ys = (float)(h - 1) * (float)y / (float)(H - 1);
    float xs = (float)(w - 1) * (float)x / (float)(W - 1);
    int y0 = (int)floorf(ys), x0 = (int)floorf(xs);
    float wy = ys - (float)y0, wx = xs - (float)x0;
    int y1 = min(y0 + 1, h - 1), x1 = min(x0 + 1, w - 1);
    const float* p = in + (size_t)nc * h * w;
    float a = p[y0 * w + x0] * (1.f - wy) + p[y1 * w + x0] * wy;
    float b = p[y0 * w + x1] * (1.f - wy) + p[y1 * w + x1] * wy;
    out[i] = 2.0f * (a * (1.f - wx) + b * wx);
}

// build 8-channel conv input: [ref(3), warp(supp,flow_up)(3), flow_up(2)]
__global__ void k_prepare(const float* __restrict__ r, const float* __restrict__ s,
                          const float* __restrict__ fup, float* __restrict__ out,
                          int H, int W) {
    int HW = H * W;
    int total = NB * HW;
    int i = blockIdx.x * blockDim.x + threadIdx.x;
    if (i >= total) return;
    int x = i % W;
    int y = (i / W) % H;
    int n = i / HW;
    int pix = y * W + x;
    float f0 = fup[((size_t)n * 2 + 0) * HW + pix];
    float f1 = fup[((size_t)n * 2 + 1) * HW + pix];
    float fx = fminf(fmaxf((float)x + f0, 0.f), (float)(W - 1));
    float fy = fminf(fmaxf((float)y + f1, 0.f), (float)(H - 1));
    int x0 = (int)floorf(fx), y0 = (int)floorf(fy);
    int x1 = min(x0 + 1, W - 1), y1 = min(y0 + 1, H - 1);
    float wx = fx - (float)x0, wy = fy - (float)y0;
    float* o = out + (size_t)n * 8 * HW + pix;
#pragma unroll
    for (int c = 0; c < 3; c++) {
        o[(size_t)c * HW] = r[((size_t)n * 3 + c) * HW + pix];
        const float* sp = s + ((size_t)n * 3 + c) * HW;
        float v = sp[y0 * W + x0] * (1.f - wy) * (1.f - wx)
                + sp[y0 * W + x1] * (1.f - wy) * wx
                + sp[y1 * W + x0] * wy * (1.f - wx)
                + sp[y1 * W + x1] * wy * wx;
        o[(size_t)(3 + c) * HW] = v;
    }
    o[(size_t)6 * HW] = f0;
    o[(size_t)7 * HW] = f1;
}

__global__ void k_addflow(const float* __restrict__ a, const float* __restrict__ b,
                          float* __restrict__ out, int total) {
    int i = blockIdx.x * blockDim.x + threadIdx.x;
    if (i < total) out[i] = a[i] + b[i];
}

// ---------------- 7x7 SAME conv, NCHW, OIHW weights ----------------
// block: 16x16 threads; each thread computes 2x2 pixels x 8 output channels.
// blockIdx.z = n * coutGroups + cg
#define CT 8
__global__ __launch_bounds__(256) void k_conv7(
    const float* __restrict__ in, const float* __restrict__ w,
    const float* __restrict__ bias, float* __restrict__ out,
    int Cin, int Cout, int H, int W, int relu) {
    __shared__ float s_in[38][41];   // 32+6 halo; pitch 41 -> conflict-free stride-2 reads
    __shared__ float s_w[CT][49];

    int coutGroups = (Cout + CT - 1) / CT;
    int cg = blockIdx.z % coutGroups;
    int n  = blockIdx.z / coutGroups;
    int ox0 = blockIdx.x * 32;
    int oy0 = blockIdx.y * 32;
    int tx = threadIdx.x, ty = threadIdx.y;
    int tid = ty * 16 + tx;

    float acc[4][CT];
#pragma unroll
    for (int co = 0; co < CT; co++) {
        int cout = cg * CT + co;
        float b = (cout < Cout) ? bias[cout] : 0.f;
        acc[0][co] = b; acc[1][co] = b; acc[2][co] = b; acc[3][co] = b;
    }

    for (int ci = 0; ci < Cin; ci++) {
        const float* ip = in + (size_t)(n * Cin + ci) * H * W;
        for (int idx = tid; idx < 38 * 38; idx += 256) {
            int ly = idx / 38, lx = idx % 38;
            int iy = oy0 - 3 + ly, ix = ox0 - 3 + lx;
            s_in[ly][lx] = (iy >= 0 && iy < H && ix >= 0 && ix < W)
                               ? ip[(size_t)iy * W + ix] : 0.f;
        }
        for (int idx = tid; idx < CT * 49; idx += 256) {
            int co = idx / 49, k = idx % 49;
            int cout = cg * CT + co;
            s_w[co][k] = (cout < Cout) ? w[((size_t)cout * Cin + ci) * 49 + k] : 0.f;
        }
        __syncthreads();
#pragma unroll
        for (int ky = 0; ky < 7; ky++) {
#pragma unroll
            for (int kx = 0; kx < 7; kx++) {
                float v00 = s_in[ty * 2 + ky][tx * 2 + kx];
                float v01 = s_in[ty * 2 + ky][tx * 2 + kx + 1];
                float v10 = s_in[ty * 2 + ky + 1][tx * 2 + kx];
                float v11 = s_in[ty * 2 + ky + 1][tx * 2 + kx + 1];
#pragma unroll
                for (int co = 0; co < CT; co++) {
                    float wv = s_w[co][ky * 7 + kx];
                    acc[0][co] += v00 * wv;
                    acc[1][co] += v01 * wv;
                    acc[2][co] += v10 * wv;
                    acc[3][co] += v11 * wv;
                }
            }
        }
        __syncthreads();
    }

    int oy = oy0 + ty * 2, ox = ox0 + tx * 2;
#pragma unroll
    for (int co = 0; co < CT; co++) {
        int cout = cg * CT + co;
        if (cout < Cout) {
            float* op = out + (size_t)(n * Cout + cout) * H * W;
#pragma unroll
            for (int p = 0; p < 4; p++) {
                int yy = oy + (p >> 1), xx = ox + (p & 1);
                if (yy < H && xx < W) {
                    float v = acc[p][co];
                    op[(size_t)yy * W + xx] = relu ? fmaxf(v, 0.f) : v;
                }
            }
        }
    }
}

// ---------------- driver ----------------
extern "C" void kernel_launch(void* const* d_in, const int* in_sizes, int n_in,
                              void* d_out, int out_size) {
    const float* ref  = (const float*)d_in[0];
    const float* supp = (const float*)d_in[1];
    const float* Wt[5] = {(const float*)d_in[2], (const float*)d_in[4],
                          (const float*)d_in[6], (const float*)d_in[8],
                          (const float*)d_in[10]};
    const float* Bt[5] = {(const float*)d_in[3], (const float*)d_in[5],
                          (const float*)d_in[7], (const float*)d_in[9],
                          (const float*)d_in[11]};

    float *pr, *ps, *bufA, *bufB, *flow, *fup;
    cudaGetSymbolAddress((void**)&pr,   g_pyr_ref);
    cudaGetSymbolAddress((void**)&ps,   g_pyr_supp);
    cudaGetSymbolAddress((void**)&bufA, g_bufA);
    cudaGetSymbolAddress((void**)&bufB, g_bufB);
    cudaGetSymbolAddress((void**)&flow, g_flow);
    cudaGetSymbolAddress((void**)&fup,  g_flowup);

    // pyramid offsets: level l (0 = coarsest 8x14 ... 5 = finest 256x448)
    int off[6];
    {
        int o = 0;
        for (int l = 0; l < 6; l++) {
            off[l] = o;
            o += NB * 3 * (8 << l) * (14 << l);
        }
    }

    // 1) normalize into finest level
    {
        int HW = 256 * 448;
        int total = NB * 3 * HW;
        k_normalize<<<(total + 255) / 256, 256>>>(ref, supp, pr + off[5], ps + off[5],
                                                  total, HW);
    }
    // 2) build pyramids
    for (int l = 5; l >= 1; l--) {
        int H = 8 << (l - 1), W = 14 << (l - 1);
        int total = NB * 3 * H * W;
        int g = (total + 255) / 256;
        k_avgpool<<<g, 256>>>(pr + off[l], pr + off[l - 1], total, H, W);
        k_avgpool<<<g, 256>>>(ps + off[l], ps + off[l - 1], total, H, W);
    }

    const int cins[5]  = {8, 32, 64, 32, 16};
    const int couts[5] = {32, 64, 32, 16, 2};

    // 3) coarse-to-fine
    for (int l = 0; l < 6; l++) {
        int H = 8 << l, W = 14 << l;
        int HW = H * W;
        int tflow = NB * 2 * HW;

        if (l == 0) {
            k_zero<<<(tflow + 255) / 256, 256>>>(fup, tflow);
        } else {
            k_upflow<<<(tflow + 255) / 256, 256>>>(flow, fup, H / 2, W / 2);
        }

        int tp = NB * HW;
        k_prepare<<<(tp + 255) / 256, 256>>>(pr + off[l], ps + off[l], fup, bufA, H, W);

        float* io[6] = {bufA, bufB, bufA, bufB, bufA, bufB};
        dim3 blk(16, 16);
        for (int i = 0; i < 5; i++) {
            int Cin = cins[i], Cout = couts[i];
            dim3 grd((W + 31) / 32, (H + 31) / 32, NB * ((Cout + CT - 1) / CT));
            const float* wp = Wt[i] + (size_t)l * Cout * Cin * 49;
            const float* bp = Bt[i] + (size_t)l * Cout;
            k_conv7<<<grd, blk>>>(io[i], wp, bp, io[i + 1], Cin, Cout, H, W, (i < 4) ? 1 : 0);
        }

        float* dst = (l == 5) ? (float*)d_out : flow;
        k_addflow<<<(tflow + 255) / 256, 256>>>(fup, bufB, dst, tflow);
    }
    (void)in_sizes; (void)n_in; (void)out_size;
}

// round 2
// speedup vs baseline: 1.2657x; 1.2657x over previous
#include <cuda_runtime.h>
#include <math.h>

#define NB 8   // batch

// ---------------- scratch (device globals; no allocation allowed) ----------------
__device__ float g_pyr_ref[3669120];
__device__ float g_pyr_supp[3669120];
__device__ float g_bufA[58720256];
__device__ float g_bufB[58720256];
__device__ float g_flow[1835008];
__device__ float g_flowup[1835008];

// ---------------- packed f32x2 helpers ----------------
typedef unsigned long long u64;

__device__ __forceinline__ u64 pack2(float lo, float hi) {
    u64 d;
    asm("mov.b64 %0, {%1, %2};" : "=l"(d) : "f"(lo), "f"(hi));
    return d;
}
__device__ __forceinline__ u64 dup2(float v) {
    u64 d;
    asm("mov.b64 %0, {%1, %1};" : "=l"(d) : "f"(v));
    return d;
}
__device__ __forceinline__ void unpack2(u64 v, float& lo, float& hi) {
    asm("mov.b64 {%0, %1}, %2;" : "=f"(lo), "=f"(hi) : "l"(v));
}
__device__ __forceinline__ void fma2(u64& d, u64 a, u64 b) {
    asm("fma.rn.f32x2 %0, %1, %2, %0;" : "+l"(d) : "l"(a), "l"(b));
}

// ---------------- small elementwise kernels ----------------
__global__ void k_normalize(const float* __restrict__ ref, const float* __restrict__ supp,
                            float* __restrict__ oref, float* __restrict__ osupp,
                            int total, int HW) {
    int i = blockIdx.x * blockDim.x + threadIdx.x;
    if (i >= total) return;
    int c = (i / HW) % 3;
    const float mean[3] = {0.485f, 0.456f, 0.406f};
    const float stdv[3] = {0.229f, 0.224f, 0.225f};
    oref[i]  = (ref[i]  - mean[c]) / stdv[c];
    osupp[i] = (supp[i] - mean[c]) / stdv[c];
}

__global__ void k_avgpool(const float* __restrict__ in, float* __restrict__ out,
                          int total, int H, int W) {
    int i = blockIdx.x * blockDim.x + threadIdx.x;
    if (i >= total) return;
    int x = i % W;
    int y = (i / W) % H;
    int nc = i / (W * H);
    const float* p = in + (size_t)nc * (4 * H * W) + (size_t)(2 * y) * (2 * W) + 2 * x;
    out[i] = 0.25f * (p[0] + p[1] + p[2 * W] + p[2 * W + 1]);
}

__global__ void k_zero(float* p, int total) {
    int i = blockIdx.x * blockDim.x + threadIdx.x;
    if (i < total) p[i] = 0.f;
}

__global__ void k_upflow(const float* __restrict__ in, float* __restrict__ out,
                         int h, int w) {
    int H = 2 * h, W = 2 * w;
    int total = NB * 2 * H * W;
    int i = blockIdx.x * blockDim.x + threadIdx.x;
    if (i >= total) return;
    int x = i % W;
    int y = (i / W) % H;
    int nc = i / (W * H);
    float ys = (float)(h - 1) * (float)y / (float)(H - 1);
    float xs = (float)(w - 1) * (float)x / (float)(W - 1);
    int y0 = (int)floorf(ys), x0 = (int)floorf(xs);
    float wy = ys - (float)y0, wx = xs - (float)x0;
    int y1 = min(y0 + 1, h - 1), x1 = min(x0 + 1, w - 1);
    const float* p = in + (size_t)nc * h * w;
    float a = p[y0 * w + x0] * (1.f - wy) + p[y1 * w + x0] * wy;
    float b = p[y0 * w + x1] * (1.f - wy) + p[y1 * w + x1] * wy;
    out[i] = 2.0f * (a * (1.f - wx) + b * wx);
}

__global__ void k_prepare(const float* __restrict__ r, const float* __restrict__ s,
                          const float* __restrict__ fup, float* __restrict__ out,
                          int H, int W) {
    int HW = H * W;
    int total = NB * HW;
    int i = blockIdx.x * blockDim.x + threadIdx.x;
    if (i >= total) return;
    int x = i % W;
    int y = (i / W) % H;
    int n = i / HW;
    int pix = y * W + x;
    float f0 = fup[((size_t)n * 2 + 0) * HW + pix];
    float f1 = fup[((size_t)n * 2 + 1) * HW + pix];
    float fx = fminf(fmaxf((float)x + f0, 0.f), (float)(W - 1));
    float fy = fminf(fmaxf((float)y + f1, 0.f), (float)(H - 1));
    int x0 = (int)floorf(fx), y0 = (int)floorf(fy);
    int x1 = min(x0 + 1, W - 1), y1 = min(y0 + 1, H - 1);
    float wx = fx - (float)x0, wy = fy - (float)y0;
    float* o = out + (size_t)n * 8 * HW + pix;
#pragma unroll
    for (int c = 0; c < 3; c++) {
        o[(size_t)c * HW] = r[((size_t)n * 3 + c) * HW + pix];
        const float* sp = s + ((size_t)n * 3 + c) * HW;
        float v = sp[y0 * W + x0] * (1.f - wy) * (1.f - wx)
                + sp[y0 * W + x1] * (1.f - wy) * wx
                + sp[y1 * W + x0] * wy * (1.f - wx)
                + sp[y1 * W + x1] * wy * wx;
        o[(size_t)(3 + c) * HW] = v;
    }
    o[(size_t)6 * HW] = f0;
    o[(size_t)7 * HW] = f1;
}

__global__ void k_addflow(const float* __restrict__ a, const float* __restrict__ b,
                          float* __restrict__ out, int total) {
    int i = blockIdx.x * blockDim.x + threadIdx.x;
    if (i < total) out[i] = a[i] + b[i];
}

// ---------------- 7x7 SAME conv, NCHW, OIHW, packed f32x2 ----------------
// block 16x16; each thread: 2x2 pixels x 8 output channels (4 packed co-pairs).
#define CT 8
__global__ __launch_bounds__(256) void k_conv7(
    const float* __restrict__ in, const float* __restrict__ w,
    const float* __restrict__ bias, float* __restrict__ out,
    int Cin, int Cout, int H, int W, int relu) {
    // pitch 40 floats: even -> LDS.64 8B-aligned; two rows per warp hit disjoint bank pairs
    __shared__ __align__(16) float s_in[38 * 40];
    __shared__ __align__(16) float s_w[49][CT];   // co-contiguous -> packed weight LDS.64

    int coutGroups = (Cout + CT - 1) / CT;
    int cg = blockIdx.z % coutGroups;
    int n  = blockIdx.z / coutGroups;
    int ox0 = blockIdx.x * 32;
    int oy0 = blockIdx.y * 32;
    int tx = threadIdx.x, ty = threadIdx.y;
    int tid = ty * 16 + tx;

    u64 acc[4][CT / 2];   // [pixel][co-pair]
#pragma unroll
    for (int j = 0; j < CT / 2; j++) {
        int c0 = cg * CT + 2 * j, c1 = c0 + 1;
        float b0 = (c0 < Cout) ? bias[c0] : 0.f;
        float b1 = (c1 < Cout) ? bias[c1] : 0.f;
        u64 b = pack2(b0, b1);
        acc[0][j] = b; acc[1][j] = b; acc[2][j] = b; acc[3][j] = b;
    }

    const float2* s_in2 = (const float2*)s_in;

    for (int ci = 0; ci < Cin; ci++) {
        const float* ip = in + (size_t)(n * Cin + ci) * H * W;
        for (int idx = tid; idx < 38 * 38; idx += 256) {
            int ly = idx / 38, lx = idx % 38;
            int iy = oy0 - 3 + ly, ix = ox0 - 3 + lx;
            s_in[ly * 40 + lx] = (iy >= 0 && iy < H && ix >= 0 && ix < W)
                                     ? ip[(size_t)iy * W + ix] : 0.f;
        }
        for (int idx = tid; idx < CT * 49; idx += 256) {
            int co = idx / 49, k = idx % 49;
            int cout = cg * CT + co;
            s_w[k][co] = (cout < Cout) ? w[((size_t)cout * Cin + ci) * 49 + k] : 0.f;
        }
        __syncthreads();

        float ra[8], rb[8];
        // row ty*2 into ra (base word index even -> 4 LDS.64)
        {
            int base2 = ((ty * 2) * 40 + tx * 2) >> 1;
#pragma unroll
            for (int j = 0; j < 4; j++) {
                float2 t = s_in2[base2 + j];
                ra[2 * j] = t.x; ra[2 * j + 1] = t.y;
            }
        }
#pragma unroll
        for (int ky = 0; ky < 7; ky++) {
            int base2 = ((ty * 2 + ky + 1) * 40 + tx * 2) >> 1;
#pragma unroll
            for (int j = 0; j < 4; j++) {
                float2 t = s_in2[base2 + j];
                rb[2 * j] = t.x; rb[2 * j + 1] = t.y;
            }
            u64 da = dup2(ra[0]);
            u64 db = dup2(rb[0]);
#pragma unroll
            for (int kx = 0; kx < 7; kx++) {
                u64 da1 = dup2(ra[kx + 1]);
                u64 db1 = dup2(rb[kx + 1]);
                const u64* wp = (const u64*)&s_w[ky * 7 + kx][0];
#pragma unroll
                for (int j = 0; j < CT / 2; j++) {
                    u64 wv = wp[j];
                    fma2(acc[0][j], da,  wv);
                    fma2(acc[1][j], da1, wv);
                    fma2(acc[2][j], db,  wv);
                    fma2(acc[3][j], db1, wv);
                }
                da = da1; db = db1;
            }
#pragma unroll
            for (int j = 0; j < 8; j++) ra[j] = rb[j];
        }
        __syncthreads();
    }

    int oy = oy0 + ty * 2, ox = ox0 + tx * 2;
#pragma unroll
    for (int j = 0; j < CT / 2; j++) {
        int c0 = cg * CT + 2 * j;
#pragma unroll
        for (int p = 0; p < 4; p++) {
            int yy = oy + (p >> 1), xx = ox + (p & 1);
            if (yy < H && xx < W) {
                float v0, v1;
                unpack2(acc[p][j], v0, v1);
                if (relu) { v0 = fmaxf(v0, 0.f); v1 = fmaxf(v1, 0.f); }
                if (c0 < Cout)
                    out[(size_t)(n * Cout + c0) * H * W + (size_t)yy * W + xx] = v0;
                if (c0 + 1 < Cout)
                    out[(size_t)(n * Cout + c0 + 1) * H * W + (size_t)yy * W + xx] = v1;
            }
        }
    }
}

// ---------------- driver ----------------
extern "C" void kernel_launch(void* const* d_in, const int* in_sizes, int n_in,
                              void* d_out, int out_size) {
    const float* ref  = (const float*)d_in[0];
    const float* supp = (const float*)d_in[1];
    const float* Wt[5] = {(const float*)d_in[2], (const float*)d_in[4],
                          (const float*)d_in[6], (const float*)d_in[8],
                          (const float*)d_in[10]};
    const float* Bt[5] = {(const float*)d_in[3], (const float*)d_in[5],
                          (const float*)d_in[7], (const float*)d_in[9],
                          (const float*)d_in[11]};

    float *pr, *ps, *bufA, *bufB, *flow, *fup;
    cudaGetSymbolAddress((void**)&pr,   g_pyr_ref);
    cudaGetSymbolAddress((void**)&ps,   g_pyr_supp);
    cudaGetSymbolAddress((void**)&bufA, g_bufA);
    cudaGetSymbolAddress((void**)&bufB, g_bufB);
    cudaGetSymbolAddress((void**)&flow, g_flow);
    cudaGetSymbolAddress((void**)&fup,  g_flowup);

    int off[6];
    {
        int o = 0;
        for (int l = 0; l < 6; l++) {
            off[l] = o;
            o += NB * 3 * (8 << l) * (14 << l);
        }
    }

    {
        int HW = 256 * 448;
        int total = NB * 3 * HW;
        k_normalize<<<(total + 255) / 256, 256>>>(ref, supp, pr + off[5], ps + off[5],
                                                  total, HW);
    }
    for (int l = 5; l >= 1; l--) {
        int H = 8 << (l - 1), W = 14 << (l - 1);
        int total = NB * 3 * H * W;
        int g = (total + 255) / 256;
        k_avgpool<<<g, 256>>>(pr + off[l], pr + off[l - 1], total, H, W);
        k_avgpool<<<g, 256>>>(ps + off[l], ps + off[l - 1], total, H, W);
    }

    const int cins[5]  = {8, 32, 64, 32, 16};
    const int couts[5] = {32, 64, 32, 16, 2};

    for (int l = 0; l < 6; l++) {
        int H = 8 << l, W = 14 << l;
        int HW = H * W;
        int tflow = NB * 2 * HW;

        if (l == 0) {
            k_zero<<<(tflow + 255) / 256, 256>>>(fup, tflow);
        } else {
            k_upflow<<<(tflow + 255) / 256, 256>>>(flow, fup, H / 2, W / 2);
        }

        int tp = NB * HW;
        k_prepare<<<(tp + 255) / 256, 256>>>(pr + off[l], ps + off[l], fup, bufA, H, W);

        float* io[6] = {bufA, bufB, bufA, bufB, bufA, bufB};
        dim3 blk(16, 16);
        for (int i = 0; i < 5; i++) {
            int Cin = cins[i], Cout = couts[i];
            dim3 grd((W + 31) / 32, (H + 31) / 32, NB * ((Cout + CT - 1) / CT));
            const float* wp = Wt[i] + (size_t)l * Cout * Cin * 49;
            const float* bp = Bt[i] + (size_t)l * Cout;
            k_conv7<<<grd, blk>>>(io[i], wp, bp, io[i + 1], Cin, Cout, H, W, (i < 4) ? 1 : 0);
        }

        float* dst = (l == 5) ? (float*)d_out : flow;
        k_addflow<<<(tflow + 255) / 256, 256>>>(fup, bufB, dst, tflow);
    }
    (void)in_sizes; (void)n_in; (void)out_size;
}

// round 3
// speedup vs baseline: 1.2661x; 1.0003x over previous
#include <cuda_runtime.h>
#include <math.h>

#define NB 8   // batch

// ---------------- scratch (device globals; no allocation allowed) ----------------
__device__ float g_pyr_ref[3669120];
__device__ float g_pyr_supp[3669120];
__device__ float g_bufA[58720256];
__device__ float g_bufB[58720256];
__device__ float g_flow[1835008];
__device__ float g_flowup[1835008];

// ---------------- packed f32x2 helpers ----------------
typedef unsigned long long u64;

__device__ __forceinline__ u64 pack2(float lo, float hi) {
    u64 d;
    asm("mov.b64 %0, {%1, %2};" : "=l"(d) : "f"(lo), "f"(hi));
    return d;
}
__device__ __forceinline__ u64 dup2(float v) {
    u64 d;
    asm("mov.b64 %0, {%1, %1};" : "=l"(d) : "f"(v));
    return d;
}
__device__ __forceinline__ void unpack2(u64 v, float& lo, float& hi) {
    asm("mov.b64 {%0, %1}, %2;" : "=f"(lo), "=f"(hi) : "l"(v));
}
__device__ __forceinline__ void fma2(u64& d, u64 a, u64 b) {
    asm("fma.rn.f32x2 %0, %1, %2, %0;" : "+l"(d) : "l"(a), "l"(b));
}

// ---------------- small elementwise kernels ----------------
__global__ void k_normalize(const float* __restrict__ ref, const float* __restrict__ supp,
                            float* __restrict__ oref, float* __restrict__ osupp,
                            int total, int HW) {
    int i = blockIdx.x * blockDim.x + threadIdx.x;
    if (i >= total) return;
    int c = (i / HW) % 3;
    const float mean[3] = {0.485f, 0.456f, 0.406f};
    const float stdv[3] = {0.229f, 0.224f, 0.225f};
    oref[i]  = (ref[i]  - mean[c]) / stdv[c];
    osupp[i] = (supp[i] - mean[c]) / stdv[c];
}

__global__ void k_avgpool(const float* __restrict__ in, float* __restrict__ out,
                          int total, int H, int W) {
    int i = blockIdx.x * blockDim.x + threadIdx.x;
    if (i >= total) return;
    int x = i % W;
    int y = (i / W) % H;
    int nc = i / (W * H);
    const float* p = in + (size_t)nc * (4 * H * W) + (size_t)(2 * y) * (2 * W) + 2 * x;
    out[i] = 0.25f * (p[0] + p[1] + p[2 * W] + p[2 * W + 1]);
}

__global__ void k_zero(float* p, int total) {
    int i = blockIdx.x * blockDim.x + threadIdx.x;
    if (i < total) p[i] = 0.f;
}

__global__ void k_upflow(const float* __restrict__ in, float* __restrict__ out,
                         int h, int w) {
    int H = 2 * h, W = 2 * w;
    int total = NB * 2 * H * W;
    int i = blockIdx.x * blockDim.x + threadIdx.x;
    if (i >= total) return;
    int x = i % W;
    int y = (i / W) % H;
    int nc = i / (W * H);
    float ys = (float)(h - 1) * (float)y / (float)(H - 1);
    float xs = (float)(w - 1) * (float)x / (float)(W - 1);
    int y0 = (int)floorf(ys), x0 = (int)floorf(xs);
    float wy = ys - (float)y0, wx = xs - (float)x0;
    int y1 = min(y0 + 1, h - 1), x1 = min(x0 + 1, w - 1);
    const float* p = in + (size_t)nc * h * w;
    float a = p[y0 * w + x0] * (1.f - wy) + p[y1 * w + x0] * wy;
    float b = p[y0 * w + x1] * (1.f - wy) + p[y1 * w + x1] * wy;
    out[i] = 2.0f * (a * (1.f - wx) + b * wx);
}

__global__ void k_prepare(const float* __restrict__ r, const float* __restrict__ s,
                          const float* __restrict__ fup, float* __restrict__ out,
                          int H, int W) {
    int HW = H * W;
    int total = NB * HW;
    int i = blockIdx.x * blockDim.x + threadIdx.x;
    if (i >= total) return;
    int x = i % W;
    int y = (i / W) % H;
    int n = i / HW;
    int pix = y * W + x;
    float f0 = fup[((size_t)n * 2 + 0) * HW + pix];
    float f1 = fup[((size_t)n * 2 + 1) * HW + pix];
    float fx = fminf(fmaxf((float)x + f0, 0.f), (float)(W - 1));
    float fy = fminf(fmaxf((float)y + f1, 0.f), (float)(H - 1));
    int x0 = (int)floorf(fx), y0 = (int)floorf(fy);
    int x1 = min(x0 + 1, W - 1), y1 = min(y0 + 1, H - 1);
    float wx = fx - (float)x0, wy = fy - (float)y0;
    float* o = out + (size_t)n * 8 * HW + pix;
#pragma unroll
    for (int c = 0; c < 3; c++) {
        o[(size_t)c * HW] = r[((size_t)n * 3 + c) * HW + pix];
        const float* sp = s + ((size_t)n * 3 + c) * HW;
        float v = sp[y0 * W + x0] * (1.f - wy) * (1.f - wx)
                + sp[y0 * W + x1] * (1.f - wy) * wx
                + sp[y1 * W + x0] * wy * (1.f - wx)
                + sp[y1 * W + x1] * wy * wx;
        o[(size_t)(3 + c) * HW] = v;
    }
    o[(size_t)6 * HW] = f0;
    o[(size_t)7 * HW] = f1;
}

__global__ void k_addflow(const float* __restrict__ a, const float* __restrict__ b,
                          float* __restrict__ out, int total) {
    int i = blockIdx.x * blockDim.x + threadIdx.x;
    if (i < total) out[i] = a[i] + b[i];
}

// ---------------- 7x7 SAME conv, NCHW, OIHW, packed f32x2 ----------------
// block 16x16; each thread: 2x2 pixels x 8 output channels (4 packed co-pairs).
#define CT 8
__global__ __launch_bounds__(256) void k_conv7(
    const float* __restrict__ in, const float* __restrict__ w,
    const float* __restrict__ bias, float* __restrict__ out,
    int Cin, int Cout, int H, int W, int relu) {
    // pitch 40 floats: even -> LDS.64 8B-aligned; two rows per warp hit disjoint bank pairs
    __shared__ __align__(16) float s_in[38 * 40];
    __shared__ __align__(16) float s_w[49][CT];   // co-contiguous -> packed weight LDS.64

    int coutGroups = (Cout + CT - 1) / CT;
    int cg = blockIdx.z % coutGroups;
    int n  = blockIdx.z / coutGroups;
    int ox0 = blockIdx.x * 32;
    int oy0 = blockIdx.y * 32;
    int tx = threadIdx.x, ty = threadIdx.y;
    int tid = ty * 16 + tx;

    u64 acc[4][CT / 2];   // [pixel][co-pair]
#pragma unroll
    for (int j = 0; j < CT / 2; j++) {
        int c0 = cg * CT + 2 * j, c1 = c0 + 1;
        float b0 = (c0 < Cout) ? bias[c0] : 0.f;
        float b1 = (c1 < Cout) ? bias[c1] : 0.f;
        u64 b = pack2(b0, b1);
        acc[0][j] = b; acc[1][j] = b; acc[2][j] = b; acc[3][j] = b;
    }

    const float2* s_in2 = (const float2*)s_in;

    for (int ci = 0; ci < Cin; ci++) {
        const float* ip = in + (size_t)(n * Cin + ci) * H * W;
        for (int idx = tid; idx < 38 * 38; idx += 256) {
            int ly = idx / 38, lx = idx % 38;
            int iy = oy0 - 3 + ly, ix = ox0 - 3 + lx;
            s_in[ly * 40 + lx] = (iy >= 0 && iy < H && ix >= 0 && ix < W)
                                     ? ip[(size_t)iy * W + ix] : 0.f;
        }
        for (int idx = tid; idx < CT * 49; idx += 256) {
            int co = idx / 49, k = idx % 49;
            int cout = cg * CT + co;
            s_w[k][co] = (cout < Cout) ? w[((size_t)cout * Cin + ci) * 49 + k] : 0.f;
        }
        __syncthreads();

        float ra[8], rb[8];
        // row ty*2 into ra (base word index even -> 4 LDS.64)
        {
            int base2 = ((ty * 2) * 40 + tx * 2) >> 1;
#pragma unroll
            for (int j = 0; j < 4; j++) {
                float2 t = s_in2[base2 + j];
                ra[2 * j] = t.x; ra[2 * j + 1] = t.y;
            }
        }
#pragma unroll
        for (int ky = 0; ky < 7; ky++) {
            int base2 = ((ty * 2 + ky + 1) * 40 + tx * 2) >> 1;
#pragma unroll
            for (int j = 0; j < 4; j++) {
                float2 t = s_in2[base2 + j];
                rb[2 * j] = t.x; rb[2 * j + 1] = t.y;
            }
            u64 da = dup2(ra[0]);
            u64 db = dup2(rb[0]);
#pragma unroll
            for (int kx = 0; kx < 7; kx++) {
                u64 da1 = dup2(ra[kx + 1]);
                u64 db1 = dup2(rb[kx + 1]);
                const u64* wp = (const u64*)&s_w[ky * 7 + kx][0];
#pragma unroll
                for (int j = 0; j < CT / 2; j++) {
                    u64 wv = wp[j];
                    fma2(acc[0][j], da,  wv);
                    fma2(acc[1][j], da1, wv);
                    fma2(acc[2][j], db,  wv);
                    fma2(acc[3][j], db1, wv);
                }
                da = da1; db = db1;
            }
#pragma unroll
            for (int j = 0; j < 8; j++) ra[j] = rb[j];
        }
        __syncthreads();
    }

    int oy = oy0 + ty * 2, ox = ox0 + tx * 2;
#pragma unroll
    for (int j = 0; j < CT / 2; j++) {
        int c0 = cg * CT + 2 * j;
#pragma unroll
        for (int p = 0; p < 4; p++) {
            int yy = oy + (p >> 1), xx = ox + (p & 1);
            if (yy < H && xx < W) {
                float v0, v1;
                unpack2(acc[p][j], v0, v1);
                if (relu) { v0 = fmaxf(v0, 0.f); v1 = fmaxf(v1, 0.f); }
                if (c0 < Cout)
                    out[(size_t)(n * Cout + c0) * H * W + (size_t)yy * W + xx] = v0;
                if (c0 + 1 < Cout)
                    out[(size_t)(n * Cout + c0 + 1) * H * W + (size_t)yy * W + xx] = v1;
            }
        }
    }
}

// ---------------- driver ----------------
extern "C" void kernel_launch(void* const* d_in, const int* in_sizes, int n_in,
                              void* d_out, int out_size) {
    const float* ref  = (const float*)d_in[0];
    const float* supp = (const float*)d_in[1];
    const float* Wt[5] = {(const float*)d_in[2], (const float*)d_in[4],
                          (const float*)d_in[6], (const float*)d_in[8],
                          (const float*)d_in[10]};
    const float* Bt[5] = {(const float*)d_in[3], (const float*)d_in[5],
                          (const float*)d_in[7], (const float*)d_in[9],
                          (const float*)d_in[11]};

    float *pr, *ps, *bufA, *bufB, *flow, *fup;
    cudaGetSymbolAddress((void**)&pr,   g_pyr_ref);
    cudaGetSymbolAddress((void**)&ps,   g_pyr_supp);
    cudaGetSymbolAddress((void**)&bufA, g_bufA);
    cudaGetSymbolAddress((void**)&bufB, g_bufB);
    cudaGetSymbolAddress((void**)&flow, g_flow);
    cudaGetSymbolAddress((void**)&fup,  g_flowup);

    int off[6];
    {
        int o = 0;
        for (int l = 0; l < 6; l++) {
            off[l] = o;
            o += NB * 3 * (8 << l) * (14 << l);
        }
    }

    {
        int HW = 256 * 448;
        int total = NB * 3 * HW;
        k_normalize<<<(total + 255) / 256, 256>>>(ref, supp, pr + off[5], ps + off[5],
                                                  total, HW);
    }
    for (int l = 5; l >= 1; l--) {
        int H = 8 << (l - 1), W = 14 << (l - 1);
        int total = NB * 3 * H * W;
        int g = (total + 255) / 256;
        k_avgpool<<<g, 256>>>(pr + off[l], pr + off[l - 1], total, H, W);
        k_avgpool<<<g, 256>>>(ps + off[l], ps + off[l - 1], total, H, W);
    }

    const int cins[5]  = {8, 32, 64, 32, 16};
    const int couts[5] = {32, 64, 32, 16, 2};

    for (int l = 0; l < 6; l++) {
        int H = 8 << l, W = 14 << l;
        int HW = H * W;
        int tflow = NB * 2 * HW;

        if (l == 0) {
            k_zero<<<(tflow + 255) / 256, 256>>>(fup, tflow);
        } else {
            k_upflow<<<(tflow + 255) / 256, 256>>>(flow, fup, H / 2, W / 2);
        }

        int tp = NB * HW;
        k_prepare<<<(tp + 255) / 256, 256>>>(pr + off[l], ps + off[l], fup, bufA, H, W);

        float* io[6] = {bufA, bufB, bufA, bufB, bufA, bufB};
        dim3 blk(16, 16);
        for (int i = 0; i < 5; i++) {
            int Cin = cins[i], Cout = couts[i];
            dim3 grd((W + 31) / 32, (H + 31) / 32, NB * ((Cout + CT - 1) / CT));
            const float* wp = Wt[i] + (size_t)l * Cout * Cin * 49;
            const float* bp = Bt[i] + (size_t)l * Cout;
            k_conv7<<<grd, blk>>>(io[i], wp, bp, io[i + 1], Cin, Cout, H, W, (i < 4) ? 1 : 0);
        }

        float* dst = (l == 5) ? (float*)d_out : flow;
        k_addflow<<<(tflow + 255) / 256, 256>>>(fup, bufB, dst, tflow);
    }
    (void)in_sizes; (void)n_in; (void)out_size;
}

// round 5
// speedup vs baseline: 2.2873x; 1.8066x over previous
#include <cuda_runtime.h>
#include <cuda_fp16.h>
#include <math.h>
#include <stdint.h>

#define NB 8   // batch

// ---------------- scratch (device globals; no allocation allowed) ----------------
__device__ float g_pyr_ref[3669120];
__device__ float g_pyr_supp[3669120];
__device__ float g_bufA[58720256];
__device__ float g_bufB[58720256];
__device__ float g_flow[1835008];
__device__ float g_flowup[1835008];
__device__ uint2 g_bw[400000];   // pre-split fp16 weight fragments (~3.2MB)

typedef unsigned long long u64;

// ---------------- packed f32x2 helpers (FFMA path, levels 0-2) ----------------
__device__ __forceinline__ u64 pack2(float lo, float hi) {
    u64 d; asm("mov.b64 %0, {%1, %2};" : "=l"(d) : "f"(lo), "f"(hi)); return d;
}
__device__ __forceinline__ u64 dup2(float v) {
    u64 d; asm("mov.b64 %0, {%1, %1};" : "=l"(d) : "f"(v)); return d;
}
__device__ __forceinline__ void unpack2(u64 v, float& lo, float& hi) {
    asm("mov.b64 {%0, %1}, %2;" : "=f"(lo), "=f"(hi) : "l"(v));
}
__device__ __forceinline__ void fma2(u64& d, u64 a, u64 b) {
    asm("fma.rn.f32x2 %0, %1, %2, %0;" : "+l"(d) : "l"(a), "l"(b));
}

// ---------------- mma helpers ----------------
__device__ __forceinline__ uint32_t smem_u32(const void* p) {
    uint32_t a;
    asm("{ .reg .u64 t; cvta.to.shared.u64 t, %1; cvt.u32.u64 %0, t; }" : "=r"(a) : "l"(p));
    return a;
}
__device__ __forceinline__ void ldmA(uint32_t* a, uint32_t addr) {
    asm volatile("ldmatrix.sync.aligned.m8n8.x4.shared.b16 {%0,%1,%2,%3}, [%4];"
                 : "=r"(a[0]), "=r"(a[1]), "=r"(a[2]), "=r"(a[3]) : "r"(addr));
}
__device__ __forceinline__ void mma16816(float* c, const uint32_t* a, uint32_t b0, uint32_t b1) {
    asm volatile("mma.sync.aligned.m16n8k16.row.col.f32.f16.f16.f32 "
                 "{%0,%1,%2,%3}, {%4,%5,%6,%7}, {%8,%9}, {%0,%1,%2,%3};"
                 : "+f"(c[0]), "+f"(c[1]), "+f"(c[2]), "+f"(c[3])
                 : "r"(a[0]), "r"(a[1]), "r"(a[2]), "r"(a[3]), "r"(b0), "r"(b1));
}
__device__ __forceinline__ uint32_t pack_h2(__half a, __half b) {
    __half2 h = __halves2half2(a, b);
    return *(uint32_t*)&h;
}

// ---------------- small elementwise kernels ----------------
__global__ void k_normalize(const float* __restrict__ ref, const float* __restrict__ supp,
                            float* __restrict__ oref, float* __restrict__ osupp,
                            int total, int HW) {
    int i = blockIdx.x * blockDim.x + threadIdx.x;
    if (i >= total) return;
    int c = (i / HW) % 3;
    const float mean[3] = {0.485f, 0.456f, 0.406f};
    const float stdv[3] = {0.229f, 0.224f, 0.225f};
    oref[i]  = (ref[i]  - mean[c]) / stdv[c];
    osupp[i] = (supp[i] - mean[c]) / stdv[c];
}

__global__ void k_avgpool(const float* __restrict__ in, float* __restrict__ out,
                          int total, int H, int W) {
    int i = blockIdx.x * blockDim.x + threadIdx.x;
    if (i >= total) return;
    int x = i % W;
    int y = (i / W) % H;
    int nc = i / (W * H);
    const float* p = in + (size_t)nc * (4 * H * W) + (size_t)(2 * y) * (2 * W) + 2 * x;
    out[i] = 0.25f * (p[0] + p[1] + p[2 * W] + p[2 * W + 1]);
}

__global__ void k_zero(float* p, int total) {
    int i = blockIdx.x * blockDim.x + threadIdx.x;
    if (i < total) p[i] = 0.f;
}

__global__ void k_upflow(const float* __restrict__ in, float* __restrict__ out,
                         int h, int w) {
    int H = 2 * h, W = 2 * w;
    int total = NB * 2 * H * W;
    int i = blockIdx.x * blockDim.x + threadIdx.x;
    if (i >= total) return;
    int x = i % W;
    int y = (i / W) % H;
    int nc = i / (W * H);
    float ys = (float)(h - 1) * (float)y / (float)(H - 1);
    float xs = (float)(w - 1) * (float)x / (float)(W - 1);
    int y0 = (int)floorf(ys), x0 = (int)floorf(xs);
    float wy = ys - (float)y0, wx = xs - (float)x0;
    int y1 = min(y0 + 1, h - 1), x1 = min(x0 + 1, w - 1);
    const float* p = in + (size_t)nc * h * w;
    float a = p[y0 * w + x0] * (1.f - wy) + p[y1 * w + x0] * wy;
    float b = p[y0 * w + x1] * (1.f - wy) + p[y1 * w + x1] * wy;
    out[i] = 2.0f * (a * (1.f - wx) + b * wx);
}

__global__ void k_prepare(const float* __restrict__ r, const float* __restrict__ s,
                          const float* __restrict__ fup, float* __restrict__ out,
                          int H, int W) {
    int HW = H * W;
    int total = NB * HW;
    int i = blockIdx.x * blockDim.x + threadIdx.x;
    if (i >= total) return;
    int x = i % W;
    int y = (i / W) % H;
    int n = i / HW;
    int pix = y * W + x;
    float f0 = fup[((size_t)n * 2 + 0) * HW + pix];
    float f1 = fup[((size_t)n * 2 + 1) * HW + pix];
    float fx = fminf(fmaxf((float)x + f0, 0.f), (float)(W - 1));
    float fy = fminf(fmaxf((float)y + f1, 0.f), (float)(H - 1));
    int x0 = (int)floorf(fx), y0 = (int)floorf(fy);
    int x1 = min(x0 + 1, W - 1), y1 = min(y0 + 1, H - 1);
    float wx = fx - (float)x0, wy = fy - (float)y0;
    float* o = out + (size_t)n * 8 * HW + pix;
#pragma unroll
    for (int c = 0; c < 3; c++) {
        o[(size_t)c * HW] = r[((size_t)n * 3 + c) * HW + pix];
        const float* sp = s + ((size_t)n * 3 + c) * HW;
        float v = sp[y0 * W + x0] * (1.f - wy) * (1.f - wx)
                + sp[y0 * W + x1] * (1.f - wy) * wx
                + sp[y1 * W + x0] * wy * (1.f - wx)
                + sp[y1 * W + x1] * wy * wx;
        o[(size_t)(3 + c) * HW] = v;
    }
    o[(size_t)6 * HW] = f0;
    o[(size_t)7 * HW] = f1;
}

__global__ void k_addflow(const float* __restrict__ a, const float* __restrict__ b,
                          float* __restrict__ out, int total) {
    int i = blockIdx.x * blockDim.x + threadIdx.x;
    if (i < total) out[i] = a[i] + b[i];
}

// ---------------- weight prep: B fragments in mma lane layout ----------------
// dst flat index: ((((grp*nchunks + chunk)*49 + tap)*2 + part)*NF + nf)*32 + lane -> uint2
// b0 = {W[n][k0], W[n][k0+1]}, b1 = {W[n][k0+8], W[n][k0+9]}
// n = grp*N + nf*8 + lane/4, k0 = chunk*16 + (lane%4)*2. part0=hi halves, part1=lo.
__global__ void k_wprep(const float* __restrict__ w, uint2* __restrict__ dst,
                        int Cin, int Cout, int NF, int ngrps, int nchunks) {
    int total = ngrps * nchunks * 49 * 2 * NF * 32;
    int idx = blockIdx.x * blockDim.x + threadIdx.x;
    if (idx >= total) return;
    int lane = idx & 31;
    int i2 = idx >> 5;
    int nf = i2 % NF;   i2 /= NF;
    int part = i2 % 2;  i2 /= 2;
    int tap = i2 % 49;  i2 /= 49;
    int chunk = i2 % nchunks;
    int grp = i2 / nchunks;
    int n = grp * NF * 8 + nf * 8 + (lane >> 2);
    int k0 = chunk * 16 + (lane & 3) * 2;
    float v[4];
#pragma unroll
    for (int j = 0; j < 4; j++) {
        int k = k0 + (j >> 1) * 8 + (j & 1);
        v[j] = (n < Cout && k < Cin) ? w[((size_t)n * Cin + k) * 49 + tap] : 0.f;
    }
    __half h[4];
#pragma unroll
    for (int j = 0; j < 4; j++) {
        __half hi = __float2half_rn(v[j]);
        h[j] = part == 0 ? hi : __float2half_rn(v[j] - __half2float(hi));
    }
    dst[idx] = make_uint2(pack_h2(h[0], h[1]), pack_h2(h[2], h[3]));
}

// ---------------- mma implicit-GEMM 7x7 conv (levels 3-5) ----------------
// CTA: 4 output rows x 128 output cols. A in SMEM: [part 2][10 rows][134 px][16 ci] fp16.
// Warp w: row = w>>1, xseg = (w&1)*64; M=64 per warp (4 m16 frags), N = NF*8.
#define TWm 134
#define PARTB (10 * TWm * 32)        // bytes per A part = 42880
#define ASMEM (2 * PARTB)            // 85760

template <int NF>
__global__ void __launch_bounds__(256, 2)
k_conv7_mma(const float* __restrict__ in, const uint2* __restrict__ bw,
            const float* __restrict__ bias, float* __restrict__ out,
            int Cin, int Cout, int nchunks, int H, int W, int relu) {
    extern __shared__ char smem[];
    uint32_t A0 = smem_u32(smem);

    int tid = threadIdx.x;
    int wid = tid >> 5;
    int lane = tid & 31;

    int x0 = blockIdx.x * 128;
    if (x0 > W - 128) x0 = W - 128;
    if (x0 < 0) x0 = 0;
    int y0 = blockIdx.y * 4;
    int n  = blockIdx.z % NB;
    int grp = blockIdx.z / NB;
    int cout0 = grp * NF * 8;

    int wrow = wid >> 1;
    int xs   = (wid & 1) * 64;

    float C[4][NF][4];
#pragma unroll
    for (int mi = 0; mi < 4; mi++)
#pragma unroll
        for (int nf = 0; nf < NF; nf++)
#pragma unroll
            for (int j = 0; j < 4; j++) C[mi][nf][j] = 0.f;

    uint32_t loff = (uint32_t)((lane & 15) * 32 + (lane >> 4) * 16);
    const uint2* bwg = bw + (size_t)grp * nchunks * 49 * 2 * NF * 32;

    for (int chunk = 0; chunk < nchunks; chunk++) {
        // ---- build A tile (hi/lo fp16 split), [part][row][x][ci16] ----
        int cbase = chunk * 16;
        for (int idx = tid; idx < 10 * TWm; idx += 256) {
            int r = idx / TWm, xt = idx % TWm;
            int iy = y0 - 3 + r;
            int ix = x0 - 3 + xt;
            bool vpix = (iy >= 0 && iy < H && ix >= 0 && ix < W);
            uint32_t hh[8], ll[8];
#pragma unroll
            for (int j = 0; j < 8; j++) {
                float v0 = 0.f, v1 = 0.f;
                int c0 = cbase + 2 * j;
                if (vpix) {
                    if (c0 < Cin)     v0 = in[((size_t)(n * Cin + c0) * H + iy) * W + ix];
                    if (c0 + 1 < Cin) v1 = in[((size_t)(n * Cin + c0 + 1) * H + iy) * W + ix];
                }
                __half h0 = __float2half_rn(v0);
                __half h1 = __float2half_rn(v1);
                __half l0 = __float2half_rn(v0 - __half2float(h0));
                __half l1 = __float2half_rn(v1 - __half2float(h1));
                hh[j] = pack_h2(h0, h1);
                ll[j] = pack_h2(l0, l1);
            }
            char* p0 = smem + (size_t)idx * 32;
            char* p1 = smem + PARTB + (size_t)idx * 32;
            ((uint4*)p0)[0] = make_uint4(hh[0], hh[1], hh[2], hh[3]);
            ((uint4*)p0)[1] = make_uint4(hh[4], hh[5], hh[6], hh[7]);
            ((uint4*)p1)[0] = make_uint4(ll[0], ll[1], ll[2], ll[3]);
            ((uint4*)p1)[1] = make_uint4(ll[4], ll[5], ll[6], ll[7]);
        }
        __syncthreads();

        const uint2* bwc = bwg + (size_t)chunk * 49 * 2 * NF * 32;
        uint32_t abase = A0 + loff + (uint32_t)((wrow * TWm + xs) * 32);

#pragma unroll 1
        for (int tap = 0; tap < 49; tap++) {
            int dy = tap / 7, dx = tap % 7;
            uint32_t at = abase + (uint32_t)((dy * TWm + dx) * 32);
            uint32_t ah[4][4], al[4][4];
#pragma unroll
            for (int mi = 0; mi < 4; mi++) {
                ldmA(ah[mi], at + mi * 512);
                ldmA(al[mi], at + PARTB + mi * 512);
            }
            const uint2* bt = bwc + (size_t)(tap * 2) * NF * 32;
#pragma unroll
            for (int nf = 0; nf < NF; nf++) {
                uint2 bh = bt[nf * 32 + lane];
                uint2 bl = bt[(NF + nf) * 32 + lane];
#pragma unroll
                for (int mi = 0; mi < 4; mi++) {
                    mma16816(C[mi][nf], ah[mi], bh.x, bh.y);
                    mma16816(C[mi][nf], ah[mi], bl.x, bl.y);
                    mma16816(C[mi][nf], al[mi], bh.x, bh.y);
                }
            }
        }
        __syncthreads();
    }

    // ---- epilogue ----
    int cmax = Cout - cout0;
    int y = y0 + wrow;
#pragma unroll
    for (int nf = 0; nf < NF; nf++) {
        int c = nf * 8 + (lane & 3) * 2;
        bool v0 = c < cmax, v1 = c + 1 < cmax;
        float b0 = v0 ? bias[cout0 + c] : 0.f;
        float b1 = v1 ? bias[cout0 + c + 1] : 0.f;
        float* o0 = out + ((size_t)(n * Cout + cout0 + c) * H + y) * W;
        float* o1 = o0 + (size_t)H * W;
#pragma unroll
        for (int mi = 0; mi < 4; mi++) {
            int xA = x0 + xs + mi * 16 + (lane >> 2);
            float r0 = C[mi][nf][0] + b0;
            float r1 = C[mi][nf][1] + b1;
            float r2 = C[mi][nf][2] + b0;
            float r3 = C[mi][nf][3] + b1;
            if (relu) {
                r0 = fmaxf(r0, 0.f); r1 = fmaxf(r1, 0.f);
                r2 = fmaxf(r2, 0.f); r3 = fmaxf(r3, 0.f);
            }
            if (xA < W) {
                if (v0) o0[xA] = r0;
                if (v1) o1[xA] = r1;
            }
            if (xA + 8 < W) {
                if (v0) o0[xA + 8] = r2;
                if (v1) o1[xA + 8] = r3;
            }
        }
    }
}

// ---------------- FFMA f32x2 conv (levels 0-2) ----------------
#define CT 8
__global__ __launch_bounds__(256) void k_conv7(
    const float* __restrict__ in, const float* __restrict__ w,
    const float* __restrict__ bias, float* __restrict__ out,
    int Cin, int Cout, int H, int W, int relu) {
    __shared__ __align__(16) float s_in[38 * 40];
    __shared__ __align__(16) float s_w[49][CT];

    int coutGroups = (Cout + CT - 1) / CT;
    int cg = blockIdx.z % coutGroups;
    int n  = blockIdx.z / coutGroups;
    int ox0 = blockIdx.x * 32;
    int oy0 = blockIdx.y * 32;
    int tx = threadIdx.x, ty = threadIdx.y;
    int tid = ty * 16 + tx;

    u64 acc[4][CT / 2];
#pragma unroll
    for (int j = 0; j < CT / 2; j++) {
        int c0 = cg * CT + 2 * j, c1 = c0 + 1;
        float b0 = (c0 < Cout) ? bias[c0] : 0.f;
        float b1 = (c1 < Cout) ? bias[c1] : 0.f;
        u64 b = pack2(b0, b1);
        acc[0][j] = b; acc[1][j] = b; acc[2][j] = b; acc[3][j] = b;
    }

    const float2* s_in2 = (const float2*)s_in;

    for (int ci = 0; ci < Cin; ci++) {
        const float* ip = in + (size_t)(n * Cin + ci) * H * W;
        for (int idx = tid; idx < 38 * 38; idx += 256) {
            int ly = idx / 38, lx = idx % 38;
            int iy = oy0 - 3 + ly, ix = ox0 - 3 + lx;
            s_in[ly * 40 + lx] = (iy >= 0 && iy < H && ix >= 0 && ix < W)
                                     ? ip[(size_t)iy * W + ix] : 0.f;
        }
        for (int idx = tid; idx < CT * 49; idx += 256) {
            int co = idx / 49, k = idx % 49;
            int cout = cg * CT + co;
            s_w[k][co] = (cout < Cout) ? w[((size_t)cout * Cin + ci) * 49 + k] : 0.f;
        }
        __syncthreads();

        float ra[8], rb[8];
        {
            int base2 = ((ty * 2) * 40 + tx * 2) >> 1;
#pragma unroll
            for (int j = 0; j < 4; j++) {
                float2 t = s_in2[base2 + j];
                ra[2 * j] = t.x; ra[2 * j + 1] = t.y;
            }
        }
#pragma unroll
        for (int ky = 0; ky < 7; ky++) {
            int base2 = ((ty * 2 + ky + 1) * 40 + tx * 2) >> 1;
#pragma unroll
            for (int j = 0; j < 4; j++) {
                float2 t = s_in2[base2 + j];
                rb[2 * j] = t.x; rb[2 * j + 1] = t.y;
            }
            u64 da = dup2(ra[0]);
            u64 db = dup2(rb[0]);
#pragma unroll
            for (int kx = 0; kx < 7; kx++) {
                u64 da1 = dup2(ra[kx + 1]);
                u64 db1 = dup2(rb[kx + 1]);
                const u64* wp = (const u64*)&s_w[ky * 7 + kx][0];
#pragma unroll
                for (int j = 0; j < CT / 2; j++) {
                    u64 wv = wp[j];
                    fma2(acc[0][j], da,  wv);
                    fma2(acc[1][j], da1, wv);
                    fma2(acc[2][j], db,  wv);
                    fma2(acc[3][j], db1, wv);
                }
                da = da1; db = db1;
            }
#pragma unroll
            for (int j = 0; j < 8; j++) ra[j] = rb[j];
        }
        __syncthreads();
    }

    int oy = oy0 + ty * 2, ox = ox0 + tx * 2;
#pragma unroll
    for (int j = 0; j < CT / 2; j++) {
        int c0 = cg * CT + 2 * j;
#pragma unroll
        for (int p = 0; p < 4; p++) {
            int yy = oy + (p >> 1), xx = ox + (p & 1);
            if (yy < H && xx < W) {
                float v0, v1;
                unpack2(acc[p][j], v0, v1);
                if (relu) { v0 = fmaxf(v0, 0.f); v1 = fmaxf(v1, 0.f); }
                if (c0 < Cout)
                    out[(size_t)(n * Cout + c0) * H * W + (size_t)yy * W + xx] = v0;
                if (c0 + 1 < Cout)
                    out[(size_t)(n * Cout + c0 + 1) * H * W + (size_t)yy * W + xx] = v1;
            }
        }
    }
}

// ---------------- driver ----------------
extern "C" void kernel_launch(void* const* d_in, const int* in_sizes, int n_in,
                              void* d_out, int out_size) {
    const float* ref  = (const float*)d_in[0];
    const float* supp = (const float*)d_in[1];
    const float* Wt[5] = {(const float*)d_in[2], (const float*)d_in[4],
                          (const float*)d_in[6], (const float*)d_in[8],
                          (const float*)d_in[10]};
    const float* Bt[5] = {(const float*)d_in[3], (const float*)d_in[5],
                          (const float*)d_in[7], (const float*)d_in[9],
                          (const float*)d_in[11]};

    float *pr, *ps, *bufA, *bufB, *flow, *fup;
    uint2* bw;
    cudaGetSymbolAddress((void**)&pr,   g_pyr_ref);
    cudaGetSymbolAddress((void**)&ps,   g_pyr_supp);
    cudaGetSymbolAddress((void**)&bufA, g_bufA);
    cudaGetSymbolAddress((void**)&bufB, g_bufB);
    cudaGetSymbolAddress((void**)&flow, g_flow);
    cudaGetSymbolAddress((void**)&fup,  g_flowup);
    cudaGetSymbolAddress((void**)&bw,   g_bw);

    const int cins[5]   = {8, 32, 64, 32, 16};
    const int couts[5]  = {32, 64, 32, 16, 2};
    const int NFs[5]    = {4, 4, 4, 2, 1};
    const int ngrps[5]  = {1, 2, 1, 1, 1};
    const int nchks[5]  = {1, 2, 4, 2, 1};

    cudaFuncSetAttribute(k_conv7_mma<4>, cudaFuncAttributeMaxDynamicSharedMemorySize, ASMEM);
    cudaFuncSetAttribute(k_conv7_mma<2>, cudaFuncAttributeMaxDynamicSharedMemorySize, ASMEM);
    cudaFuncSetAttribute(k_conv7_mma<1>, cudaFuncAttributeMaxDynamicSharedMemorySize, ASMEM);

    // ---- weight prep for tensor levels (3,4,5) ----
    size_t bwoff[3][5];
    {
        size_t o = 0;
        for (int li = 0; li < 3; li++) {
            int l = 3 + li;
            for (int i = 0; i < 5; i++) {
                bwoff[li][i] = o;
                int total = ngrps[i] * nchks[i] * 49 * 2 * NFs[i] * 32;
                const float* wp = Wt[i] + (size_t)l * couts[i] * cins[i] * 49;
                k_wprep<<<(total + 255) / 256, 256>>>(
                    wp, bw + o, cins[i], couts[i], NFs[i], ngrps[i], nchks[i]);
                o += (size_t)total;
            }
        }
    }

    int off[6];
    {
        int o = 0;
        for (int l = 0; l < 6; l++) {
            off[l] = o;
            o += NB * 3 * (8 << l) * (14 << l);
        }
    }

    {
        int HW = 256 * 448;
        int total = NB * 3 * HW;
        k_normalize<<<(total + 255) / 256, 256>>>(ref, supp, pr + off[5], ps + off[5],
                                                  total, HW);
    }
    for (int l = 5; l >= 1; l--) {
        int H = 8 << (l - 1), W = 14 << (l - 1);
        int total = NB * 3 * H * W;
        int g = (total + 255) / 256;
        k_avgpool<<<g, 256>>>(pr + off[l], pr + off[l - 1], total, H, W);
        k_avgpool<<<g, 256>>>(ps + off[l], ps + off[l - 1], total, H, W);
    }

    for (int l = 0; l < 6; l++) {
        int H = 8 << l, W = 14 << l;
        int HW = H * W;
        int tflow = NB * 2 * HW;

        if (l == 0) {
            k_zero<<<(tflow + 255) / 256, 256>>>(fup, tflow);
        } else {
            k_upflow<<<(tflow + 255) / 256, 256>>>(flow, fup, H / 2, W / 2);
        }

        int tp = NB * HW;
        k_prepare<<<(tp + 255) / 256, 256>>>(pr + off[l], ps + off[l], fup, bufA, H, W);

        float* io[6] = {bufA, bufB, bufA, bufB, bufA, bufB};
        if (l < 3) {
            dim3 blk(16, 16);
            for (int i = 0; i < 5; i++) {
                int Cin = cins[i], Cout = couts[i];
                dim3 grd((W + 31) / 32, (H + 31) / 32, NB * ((Cout + CT - 1) / CT));
                const float* wp = Wt[i] + (size_t)l * Cout * Cin * 49;
                const float* bp = Bt[i] + (size_t)l * Cout;
                k_conv7<<<grd, blk>>>(io[i], wp, bp, io[i + 1], Cin, Cout, H, W,
                                      (i < 4) ? 1 : 0);
            }
        } else {
            int li = l - 3;
            for (int i = 0; i < 5; i++) {
                int Cin = cins[i], Cout = couts[i];
                int nx = (W + 127) / 128;
                dim3 grd(nx, H / 4, NB * ngrps[i]);
                const float* bp = Bt[i] + (size_t)l * Cout;
                const uint2* bwp = bw + bwoff[li][i];
                if (NFs[i] == 4)
                    k_conv7_mma<4><<<grd, 256, ASMEM>>>(io[i], bwp, bp, io[i + 1],
                                                        Cin, Cout, nchks[i], H, W, (i < 4));
                else if (NFs[i] == 2)
                    k_conv7_mma<2><<<grd, 256, ASMEM>>>(io[i], bwp, bp, io[i + 1],
                                                        Cin, Cout, nchks[i], H, W, (i < 4));
                else
                    k_conv7_mma<1><<<grd, 256, ASMEM>>>(io[i], bwp, bp, io[i + 1],
                                                        Cin, Cout, nchks[i], H, W, (i < 4));
            }
        }

        float* dst = (l == 5) ? (float*)d_out : flow;
        k_addflow<<<(tflow + 255) / 256, 256>>>(fup, bufB, dst, tflow);
    }
    (void)in_sizes; (void)n_in; (void)out_size;
}